// round 14
// baseline (speedup 1.0000x reference)
#include <cuda_runtime.h>
#include <cuda_bf16.h>
#include <math.h>
#include <stdint.h>

#define S 2048
#define D 64
#define NH 32
#define SCALE 0.125f
#define STR 72            // smem row stride in bf16 (64 data + 8 pad)

// per-(head, 128-wide k-tile, row) partial sums of exp(s)
__device__ float g_stats[(size_t)NH * 16 * S];
// split-K partial O over 512-wide k-quads: [h][qt][p<4][128*64]
__device__ float g_part[(size_t)NH * 16 * 4 * 128 * 64];
// completion counters per (h, qt)
__device__ int g_cnt[NH * 16];
// scratch O for the weights-only branch
__device__ float g_Oscratch[(size_t)NH * S * D];
// pre-split bf16 K/V: [h][tile][plane hi/lo][128][64]
__device__ __align__(16) __nv_bfloat16 g_kbf[(size_t)NH * 16 * 2 * 128 * 64];
__device__ __align__(16) __nv_bfloat16 g_vbf[(size_t)NH * 16 * 2 * 128 * 64];

// ------------------------------ helpers -----------------------------------
__device__ __forceinline__ uint32_t smem_u32(const void* p) {
    return (uint32_t)__cvta_generic_to_shared(p);
}
__device__ __forceinline__ void cpa16(uint32_t dst, const void* src) {
    asm volatile("cp.async.ca.shared.global [%0], [%1], 16;\n" :: "r"(dst), "l"(src));
}
__device__ __forceinline__ void cpa_commit() {
    asm volatile("cp.async.commit_group;\n" ::: "memory");
}
template <int N>
__device__ __forceinline__ void cpa_wait() {
    asm volatile("cp.async.wait_group %0;\n" :: "n"(N) : "memory");
}
__device__ __forceinline__ void ldsm4(uint32_t* r, uint32_t addr) {
    asm volatile("ldmatrix.sync.aligned.m8n8.x4.shared.b16 {%0,%1,%2,%3}, [%4];"
                 : "=r"(r[0]), "=r"(r[1]), "=r"(r[2]), "=r"(r[3]) : "r"(addr));
}
__device__ __forceinline__ void ldsm4t(uint32_t* r, uint32_t addr) {
    asm volatile("ldmatrix.sync.aligned.m8n8.x4.trans.shared.b16 {%0,%1,%2,%3}, [%4];"
                 : "=r"(r[0]), "=r"(r[1]), "=r"(r[2]), "=r"(r[3]) : "r"(addr));
}
__device__ __forceinline__ void ldsm2(uint32_t* r, uint32_t addr) {
    asm volatile("ldmatrix.sync.aligned.m8n8.x2.shared.b16 {%0,%1}, [%2];"
                 : "=r"(r[0]), "=r"(r[1]) : "r"(addr));
}
__device__ __forceinline__ void mma_bf16(float* c, const uint32_t* a, const uint32_t* b) {
    asm volatile("mma.sync.aligned.m16n8k16.row.col.f32.bf16.bf16.f32 "
                 "{%0,%1,%2,%3},{%4,%5,%6,%7},{%8,%9},{%0,%1,%2,%3};"
                 : "+f"(c[0]), "+f"(c[1]), "+f"(c[2]), "+f"(c[3])
                 : "r"(a[0]), "r"(a[1]), "r"(a[2]), "r"(a[3]), "r"(b[0]), "r"(b[1]));
}
__device__ __forceinline__ void split2x(float4 v, uint2& hv, uint2& lv) {
    __nv_bfloat16 h0 = __float2bfloat16(v.x), h1 = __float2bfloat16(v.y);
    __nv_bfloat16 h2 = __float2bfloat16(v.z), h3 = __float2bfloat16(v.w);
    __nv_bfloat16 l0 = __float2bfloat16(v.x - __bfloat162float(h0));
    __nv_bfloat16 l1 = __float2bfloat16(v.y - __bfloat162float(h1));
    __nv_bfloat16 l2 = __float2bfloat16(v.z - __bfloat162float(h2));
    __nv_bfloat16 l3 = __float2bfloat16(v.w - __bfloat162float(h3));
    hv = make_uint2((uint32_t)__bfloat16_as_ushort(h0) | ((uint32_t)__bfloat16_as_ushort(h1) << 16),
                    (uint32_t)__bfloat16_as_ushort(h2) | ((uint32_t)__bfloat16_as_ushort(h3) << 16));
    lv = make_uint2((uint32_t)__bfloat16_as_ushort(l0) | ((uint32_t)__bfloat16_as_ushort(l1) << 16),
                    (uint32_t)__bfloat16_as_ushort(l2) | ((uint32_t)__bfloat16_as_ushort(l3) << 16));
}
__device__ __forceinline__ void split4(__nv_bfloat16* hi, __nv_bfloat16* lo,
                                       int off, float4 v) {
    uint2 hv, lv;
    split2x(v, hv, lv);
    *(uint2*)(hi + off) = hv;
    *(uint2*)(lo + off) = lv;
}
__device__ __forceinline__ uint32_t pk2(float a, float b) {
    __nv_bfloat162 h = __floats2bfloat162_rn(a, b);
    return *(uint32_t*)&h;
}

__device__ __forceinline__ void stage_q(const float* Qh, int q0, int t,
                                        __nv_bfloat16* Qhi, __nv_bfloat16* Qlo) {
    for (int e = t; e < 128 * 16; e += 256) {
        int r = e >> 4, c4 = e & 15;
        float4 q4 = *(const float4*)(Qh + (size_t)(q0 + r) * D + (c4 << 2));
        q4.x *= SCALE; q4.y *= SCALE; q4.z *= SCALE; q4.w *= SCALE;
        split4(Qhi, Qlo, r * STR + (c4 << 2), q4);
    }
}
__device__ __forceinline__ void stage_k(const float* Kh, int k0, int t,
                                        __nv_bfloat16* Khi, __nv_bfloat16* Klo) {
    for (int e = t; e < 128 * 16; e += 256) {
        int r = e >> 4, c4 = e & 15;
        float4 k4 = *(const float4*)(Kh + (size_t)(k0 + r) * D + (c4 << 2));
        split4(Khi, Klo, r * STR + (c4 << 2), k4);
    }
}

// ---------------------------------------------------------------------------
// K1: stats — full-precision QK per 256-wide k-pair, rowsums -> g_stats.
// Masked-band CTAs zero-fill W and convert K/V tiles to bf16 scratch.
// ---------------------------------------------------------------------------
__global__ __launch_bounds__(256, 3)
void stats_mma(const float* __restrict__ Q, const float* __restrict__ Km,
               const float* __restrict__ Vm, float* __restrict__ W) {
    int p = blockIdx.x, qt = 15 - blockIdx.y, h = blockIdx.z;
    int kt0 = p << 1;
    int q0 = qt << 7;
    int t = threadIdx.x;
    float* Wh = W + (size_t)h * S * S;

    if (p == 0 && t == 0) g_cnt[(h << 4) + qt] = 0;   // reset emit counter

    if (kt0 > qt) {                      // masked band: final W is 0
        float4 z = make_float4(0.f, 0.f, 0.f, 0.f);
        int c0 = kt0 << 7;
        for (int e = t; e < 128 * 64; e += 256) {
            int r = e >> 6, c4 = e & 63;
            __stcs((float4*)(Wh + (size_t)(q0 + r) * S + c0 + (c4 << 2)), z);
        }
        // K/V bf16 conversion — exactly once per (h, tile-pair)
        int ct = -1;
        if (qt == kt0 - 1) ct = kt0;                 // tiles 2..15
        else if (kt0 == 14 && qt == 0) ct = 0;       // tiles 0, 1
        if (ct >= 0) {
            for (int tile = ct; tile < ct + 2; tile++) {
                const float* Ks = Km + (size_t)h * S * D + (size_t)tile * 128 * D;
                const float* Vs = Vm + (size_t)h * S * D + (size_t)tile * 128 * D;
                __nv_bfloat16* kb = g_kbf + ((size_t)(h * 16 + tile) * 2) * 8192;
                __nv_bfloat16* vb = g_vbf + ((size_t)(h * 16 + tile) * 2) * 8192;
                for (int e = t; e < 128 * 16; e += 256) {
                    int r = e >> 4, c4 = e & 15;
                    uint2 hv, lv;
                    split2x(*(const float4*)(Ks + r * D + (c4 << 2)), hv, lv);
                    *(uint2*)(kb + r * 64 + (c4 << 2)) = hv;
                    *(uint2*)(kb + 8192 + r * 64 + (c4 << 2)) = lv;
                    split2x(*(const float4*)(Vs + r * D + (c4 << 2)), hv, lv);
                    *(uint2*)(vb + r * 64 + (c4 << 2)) = hv;
                    *(uint2*)(vb + 8192 + r * 64 + (c4 << 2)) = lv;
                }
            }
        }
        return;
    }

    extern __shared__ char smraw[];
    __nv_bfloat16* Qhi = (__nv_bfloat16*)smraw;
    __nv_bfloat16* Qlo = Qhi + 128 * STR;
    __nv_bfloat16* Khi = Qlo + 128 * STR;
    __nv_bfloat16* Klo = Khi + 128 * STR;

    stage_q(Q + (size_t)h * S * D, q0, t, Qhi, Qlo);

    const float* Kh = Km + (size_t)h * S * D;
    int w = t >> 5, L = t & 31;
    int wr = w << 4;
    int g = L >> 2, q = L & 3;
    int gi0 = q0 + wr + g, gi1 = gi0 + 8;
    uint32_t qhiB = smem_u32(Qhi), qloB = smem_u32(Qlo);
    uint32_t khiB = smem_u32(Khi), kloB = smem_u32(Klo);

#pragma unroll 1
    for (int sub = 0; sub < 2; sub++) {
        int kt = kt0 + sub;
        if (kt > qt) break;
        int k0 = kt << 7;
        __syncthreads();
        stage_k(Kh, k0, t, Khi, Klo);
        __syncthreads();

        uint32_t ah[4][4], al[4][4];
#pragma unroll
        for (int kk = 0; kk < 4; kk++) {
            uint32_t aoff = (uint32_t)(((wr + (L & 15)) * STR + (kk << 4) + ((L >> 4) << 3)) << 1);
            ldsm4(ah[kk], qhiB + aoff);
            ldsm4(al[kk], qloB + aoff);
        }

        float s0 = 0.f, s1 = 0.f;
        bool diag = (kt == qt);
#pragma unroll
        for (int n = 0; n < 16; n++) {
            float acc[4] = {0.f, 0.f, 0.f, 0.f};
#pragma unroll
            for (int kk = 0; kk < 4; kk++) {
                uint32_t boff = (uint32_t)((((n << 3) + (L & 7)) * STR +
                                            (kk << 4) + (((L >> 3) & 1) << 3)) << 1);
                uint32_t bh[2], bl[2];
                ldsm2(bh, khiB + boff);
                ldsm2(bl, kloB + boff);
                mma_bf16(acc, ah[kk], bh);
                mma_bf16(acc, ah[kk], bl);
                mma_bf16(acc, al[kk], bh);
            }
            if (diag) {
                int cg = k0 + (n << 3) + (q << 1);
                s0 += ((cg > gi0) ? 0.f : __expf(acc[0])) +
                      ((cg + 1 > gi0) ? 0.f : __expf(acc[1]));
                s1 += ((cg > gi1) ? 0.f : __expf(acc[2])) +
                      ((cg + 1 > gi1) ? 0.f : __expf(acc[3]));
            } else {
                s0 += __expf(acc[0]) + __expf(acc[1]);
                s1 += __expf(acc[2]) + __expf(acc[3]);
            }
        }
        s0 += __shfl_xor_sync(0xffffffffu, s0, 1);
        s0 += __shfl_xor_sync(0xffffffffu, s0, 2);
        s1 += __shfl_xor_sync(0xffffffffu, s1, 1);
        s1 += __shfl_xor_sync(0xffffffffu, s1, 2);
        if (q == 0) {
            size_t sb = (size_t)(h * 16 + kt) * S;
            g_stats[sb + gi0] = s0;
            g_stats[sb + gi1] = s1;
        }
    }

    // odd-straddle: qt even & kt0 == qt -> tile kt0+1 is fully masked
    if (kt0 == qt && kt0 + 1 <= 15) {
        float4 z = make_float4(0.f, 0.f, 0.f, 0.f);
        int c0 = (kt0 + 1) << 7;
        for (int e = t; e < 128 * 32; e += 256) {
            int r = e >> 5, c4 = e & 31;
            __stcs((float4*)(Wh + (size_t)(q0 + r) * S + c0 + (c4 << 2)), z);
        }
    }
}

// ---------------------------------------------------------------------------
// K2: emit — cp.async double-buffered pipeline over 64-row half-tiles.
// Per (h, qt, 512-wide k-quad): QK (3-MMA, A-frags in regs), W = exp(s)*Linv,
// fused PV (ldmatrix.trans); quad-partial O -> g_part; last CTA reduces.
// ---------------------------------------------------------------------------
__global__ __launch_bounds__(256, 2)
void emit_mma(const float* __restrict__ Q, float* __restrict__ W,
              float* __restrict__ O) {
    int p = blockIdx.x, qt = 15 - blockIdx.y, h = blockIdx.z;
    int kt0 = p << 2;
    if (kt0 > qt) return;
    float* Wh = W + (size_t)h * S * S;
    int q0 = qt << 7;
    int t = threadIdx.x;

    extern __shared__ char smraw[];
    __shared__ float Ls[128];
    __shared__ float Osm[128][68];
    __shared__ int isLast;

    if (t < 128) {
        float Lsum = 0.f;
        for (int k2 = 0; k2 <= qt; k2++)
            Lsum += g_stats[(size_t)(h * 16 + k2) * S + q0 + t];
        Ls[t] = 1.f / Lsum;
    }

    // stage Q temporarily, preload A fragments, then free the smem for buffers
    __nv_bfloat16* Qhi = (__nv_bfloat16*)smraw;
    __nv_bfloat16* Qlo = Qhi + 128 * STR;
    stage_q(Q + (size_t)h * S * D, q0, t, Qhi, Qlo);
    __syncthreads();

    int w = t >> 5, L = t & 31;
    int wr = w << 4;
    int g = L >> 2, q = L & 3;
    int gi0 = q0 + wr + g, gi1 = gi0 + 8;
    float li0 = Ls[wr + g], li1 = Ls[wr + 8 + g];

    uint32_t qhiB = smem_u32(Qhi), qloB = smem_u32(Qlo);
    uint32_t ahq[4][4], alq[4][4];
#pragma unroll
    for (int kk = 0; kk < 4; kk++) {
        uint32_t aoff = (uint32_t)(((wr + (L & 15)) * STR + (kk << 4) + ((L >> 4) << 3)) << 1);
        ldsm4(ahq[kk], qhiB + aoff);
        ldsm4(alq[kk], qloB + aoff);
    }
    __syncthreads();    // Q smem now reusable as pipeline buffers

    uint32_t sbase = smem_u32(smraw);
    int nsub = qt - kt0 + 1; if (nsub > 4) nsub = 4;
    int nch = nsub << 1;

    // issue cp.async loads for chunk c into buffer c&1
    auto issue = [&](int c) {
        int sub = c >> 1, half = c & 1, kt = kt0 + sub;
        uint32_t dst = sbase + (uint32_t)(c & 1) * 36864u;
        size_t kb = ((size_t)(h * 16 + kt) * 2) * 8192 + (size_t)half * 64 * 64;
#pragma unroll
        for (int i = 0; i < 8; i++) {
            int idx = t + (i << 8);
            int plane = idx >> 9;          // 0 Khi, 1 Klo, 2 Vhi, 3 Vlo
            int rem = idx & 511;
            int r = rem >> 3, c16 = rem & 7;
            const __nv_bfloat16* src = (plane < 2 ? g_kbf : g_vbf)
                + kb + (size_t)(plane & 1) * 8192 + r * 64 + (c16 << 3);
            cpa16(dst + (uint32_t)plane * 9216u + (uint32_t)(r * 144) + (uint32_t)(c16 << 4), src);
        }
    };

    issue(0); cpa_commit();

#pragma unroll 1
    for (int c = 0; c < nch; c++) {
        if (c + 1 < nch) { issue(c + 1); cpa_commit(); cpa_wait<1>(); }
        else cpa_wait<0>();
        __syncthreads();

        uint32_t b = sbase + (uint32_t)(c & 1) * 36864u;
        uint32_t khiB = b, kloB = b + 9216u, vhiB = b + 18432u, vloB = b + 27648u;
        int sub = c >> 1, half = c & 1, kt = kt0 + sub;
        int k0c = (kt << 7) + (half << 6);
        bool diag = (kt == qt);

        // QK over this 64-col half: acc[8][4]
        float acc[8][4];
#pragma unroll
        for (int n = 0; n < 8; n++)
#pragma unroll
            for (int i = 0; i < 4; i++) acc[n][i] = 0.f;
#pragma unroll
        for (int kk = 0; kk < 4; kk++) {
#pragma unroll
            for (int n2 = 0; n2 < 4; n2++) {
                uint32_t boff = (uint32_t)((((n2 << 4) + ((L >> 4) << 3) + (L & 7)) * STR +
                                            (kk << 4) + (((L >> 3) & 1) << 3)) << 1);
                uint32_t bh[4], bl[4];
                ldsm4(bh, khiB + boff);
                ldsm4(bl, kloB + boff);
                mma_bf16(acc[2 * n2],     ahq[kk], &bh[0]);
                mma_bf16(acc[2 * n2],     ahq[kk], &bl[0]);
                mma_bf16(acc[2 * n2],     alq[kk], &bh[0]);
                mma_bf16(acc[2 * n2 + 1], ahq[kk], &bh[2]);
                mma_bf16(acc[2 * n2 + 1], ahq[kk], &bl[2]);
                mma_bf16(acc[2 * n2 + 1], alq[kk], &bh[2]);
            }
        }

        // epilogue: exp + W store + fused PV over this half's 64 j values
        float acc_o[8][4];
#pragma unroll
        for (int n = 0; n < 8; n++)
#pragma unroll
            for (int i = 0; i < 4; i++) acc_o[n][i] = 0.f;

#pragma unroll
        for (int kk = 0; kk < 4; kk++) {
            float uE[4], uO[4];
#pragma unroll
            for (int h2 = 0; h2 < 2; h2++) {
                float* u = h2 ? uO : uE;
                int n = (kk << 1) + h2;
                int cg = k0c + (n << 3) + (q << 1);
                u[0] = (diag && cg > gi0) ? 0.f : __expf(acc[n][0]);
                u[1] = (diag && cg + 1 > gi0) ? 0.f : __expf(acc[n][1]);
                u[2] = (diag && cg > gi1) ? 0.f : __expf(acc[n][2]);
                u[3] = (diag && cg + 1 > gi1) ? 0.f : __expf(acc[n][3]);
                __stcs((float2*)(Wh + (size_t)gi0 * S + cg),
                       make_float2(u[0] * li0, u[1] * li0));
                __stcs((float2*)(Wh + (size_t)gi1 * S + cg),
                       make_float2(u[2] * li1, u[3] * li1));
            }
            uint32_t ah[4], al[4];
            ah[0] = pk2(uE[0], uE[1]); ah[1] = pk2(uE[2], uE[3]);
            ah[2] = pk2(uO[0], uO[1]); ah[3] = pk2(uO[2], uO[3]);
            al[0] = pk2(uE[0] - __bfloat162float(__float2bfloat16(uE[0])),
                        uE[1] - __bfloat162float(__float2bfloat16(uE[1])));
            al[1] = pk2(uE[2] - __bfloat162float(__float2bfloat16(uE[2])),
                        uE[3] - __bfloat162float(__float2bfloat16(uE[3])));
            al[2] = pk2(uO[0] - __bfloat162float(__float2bfloat16(uO[0])),
                        uO[1] - __bfloat162float(__float2bfloat16(uO[1])));
            al[3] = pk2(uO[2] - __bfloat162float(__float2bfloat16(uO[2])),
                        uO[3] - __bfloat162float(__float2bfloat16(uO[3])));

#pragma unroll
            for (int dn2 = 0; dn2 < 4; dn2++) {
                uint32_t boff = (uint32_t)((((kk << 4) + (L & 15)) * STR +
                                            (dn2 << 4) + (((L >> 4) & 1) << 3)) << 1);
                uint32_t bh[4], bl[4];
                ldsm4t(bh, vhiB + boff);
                ldsm4t(bl, vloB + boff);
                mma_bf16(acc_o[2 * dn2],     ah, &bh[0]);
                mma_bf16(acc_o[2 * dn2],     ah, &bl[0]);
                mma_bf16(acc_o[2 * dn2],     al, &bh[0]);
                mma_bf16(acc_o[2 * dn2 + 1], ah, &bh[2]);
                mma_bf16(acc_o[2 * dn2 + 1], ah, &bl[2]);
                mma_bf16(acc_o[2 * dn2 + 1], al, &bh[2]);
            }
        }

        if (c == 0) {
#pragma unroll
            for (int dn = 0; dn < 8; dn++) {
                int cc = (dn << 3) + (q << 1);
                Osm[wr + g][cc]         = acc_o[dn][0];
                Osm[wr + g][cc + 1]     = acc_o[dn][1];
                Osm[wr + 8 + g][cc]     = acc_o[dn][2];
                Osm[wr + 8 + g][cc + 1] = acc_o[dn][3];
            }
        } else {
#pragma unroll
            for (int dn = 0; dn < 8; dn++) {
                int cc = (dn << 3) + (q << 1);
                Osm[wr + g][cc]         += acc_o[dn][0];
                Osm[wr + g][cc + 1]     += acc_o[dn][1];
                Osm[wr + 8 + g][cc]     += acc_o[dn][2];
                Osm[wr + 8 + g][cc + 1] += acc_o[dn][3];
            }
        }
        __syncthreads();   // buffer c&1 free before issue(c+2) overwrites it
    }

    // raw quad-partial O
    float* P = g_part + (((size_t)(h * 16 + qt) << 2) + p) * (128 * 64);
#pragma unroll
    for (int dn = 0; dn < 8; dn++) {
        int cc = (dn << 3) + (q << 1);
        *(float2*)(P + (wr + g) * 64 + cc) =
            make_float2(Osm[wr + g][cc], Osm[wr + g][cc + 1]);
        *(float2*)(P + (wr + 8 + g) * 64 + cc) =
            make_float2(Osm[wr + 8 + g][cc], Osm[wr + 8 + g][cc + 1]);
    }

    // last CTA for this (h, qt) reduces partials and writes O
    __threadfence();
    __syncthreads();
    int np = (qt >> 2) + 1;
    if (t == 0) {
        int old = atomicAdd(&g_cnt[(h << 4) + qt], 1);
        isLast = (old == np - 1) ? 1 : 0;
    }
    __syncthreads();
    if (isLast) {
        __threadfence();
        const float* Pb = g_part + ((size_t)(h * 16 + qt) << 2) * (128 * 64);
        float* Oh = O + (size_t)h * S * D;
        for (int f = t; f < 2048; f += 256) {
            float4 s = make_float4(0.f, 0.f, 0.f, 0.f);
            for (int pp = 0; pp < np; pp++) {
                float4 v = __ldcg((const float4*)(Pb + (size_t)pp * (128 * 64) + (f << 2)));
                s.x += v.x; s.y += v.y; s.z += v.z; s.w += v.w;
            }
            float li = Ls[f >> 4];
            *(float4*)(Oh + (size_t)q0 * D + (f << 2)) =
                make_float4(s.x * li, s.y * li, s.z * li, s.w * li);
        }
    }
}

// ---------------------------------------------------------------------------
// fallback (output-only branch)
// ---------------------------------------------------------------------------
__global__ void fallback_kernel(const float* __restrict__ Q,
                                const float* __restrict__ K,
                                const float* __restrict__ V,
                                float* __restrict__ O) {
    int i = blockIdx.x, h = blockIdx.y;
    const float* Qh = Q + (size_t)h * S * D;
    const float* Kh = K + (size_t)h * S * D;
    const float* Vh = V + (size_t)h * S * D;
    float* Oh = O + (size_t)h * S * D;
    __shared__ float p[S];
    __shared__ float qsh[D];
    __shared__ float red[64];
    int t = threadIdx.x;
    qsh[t] = Qh[(size_t)i * D + t];
    __syncthreads();
    float lsum = 0.f;
    for (int j = t; j <= i; j += 64) {
        const float* kr = Kh + (size_t)j * D;
        float s = 0.f;
#pragma unroll 16
        for (int d = 0; d < D; d++) s = fmaf(qsh[d], kr[d], s);
        float e = __expf(s * SCALE);
        p[j] = e; lsum += e;
    }
    red[t] = lsum; __syncthreads();
    for (int s2 = 32; s2 > 0; s2 >>= 1) { if (t < s2) red[t] += red[t + s2]; __syncthreads(); }
    float inv = 1.0f / red[0];
    __syncthreads();
    float o = 0.f;
    for (int j = 0; j <= i; j++) o = fmaf(p[j], Vh[(size_t)j * D + t], o);
    Oh[(size_t)i * D + t] = o * inv;
}

// ---------------------------------------------------------------------------
extern "C" void kernel_launch(void* const* d_in, const int* in_sizes, int n_in,
                              void* d_out, int out_size) {
    const float* Q = (const float*)d_in[0];
    const float* K = (const float*)d_in[1];
    const float* V = (const float*)d_in[2];
    float* out = (float*)d_out;

    const long long O_ELEMS = (long long)NH * S * D;
    const long long W_ELEMS = (long long)NH * S * S;

    const int SMEM_TILES = 4 * 128 * STR * 2;   // 73728 B
    cudaFuncSetAttribute(stats_mma, cudaFuncAttributeMaxDynamicSharedMemorySize, SMEM_TILES);
    cudaFuncSetAttribute(emit_mma,  cudaFuncAttributeMaxDynamicSharedMemorySize, SMEM_TILES);

    if ((long long)out_size >= O_ELEMS + W_ELEMS) {
        float* W = out + O_ELEMS;
        stats_mma<<<dim3(8, 16, 32), 256, SMEM_TILES>>>(Q, K, V, W);
        emit_mma<<<dim3(4, 16, 32), 256, SMEM_TILES>>>(Q, W, out);
    } else if ((long long)out_size == W_ELEMS) {
        float* W = out;
        float* Oscratch;
        cudaGetSymbolAddress((void**)&Oscratch, g_Oscratch);
        stats_mma<<<dim3(8, 16, 32), 256, SMEM_TILES>>>(Q, K, V, W);
        emit_mma<<<dim3(4, 16, 32), 256, SMEM_TILES>>>(Q, W, Oscratch);
    } else {
        fallback_kernel<<<dim3(S, NH), 64>>>(Q, K, V, out);
    }
}

// round 15
// speedup vs baseline: 1.0909x; 1.0909x over previous
#include <cuda_runtime.h>
#include <cuda_bf16.h>
#include <math.h>
#include <stdint.h>

#define S 2048
#define D 64
#define NH 32
#define SCALE 0.125f
#define STR 72            // smem row stride in bf16 (64 data + 8 pad)

// per-(head, 128-wide k-tile, row) partial sums of exp(s)
__device__ float g_stats[(size_t)NH * 16 * S];
// split-K partial O over 512-wide k-quads: [h][qt][p<4][128*64]
__device__ float g_part[(size_t)NH * 16 * 4 * 128 * 64];
// completion counters per (h, qt)
__device__ int g_cnt[NH * 16];
// scratch O for the weights-only branch
__device__ float g_Oscratch[(size_t)NH * S * D];
// pre-split bf16 K/V: [h][tile][plane hi/lo][128][64]
__device__ __align__(16) __nv_bfloat16 g_kbf[(size_t)NH * 16 * 2 * 128 * 64];
__device__ __align__(16) __nv_bfloat16 g_vbf[(size_t)NH * 16 * 2 * 128 * 64];

// ------------------------------ helpers -----------------------------------
__device__ __forceinline__ uint32_t smem_u32(const void* p) {
    return (uint32_t)__cvta_generic_to_shared(p);
}
__device__ __forceinline__ void cpa16(uint32_t dst, const void* src) {
    asm volatile("cp.async.ca.shared.global [%0], [%1], 16;\n" :: "r"(dst), "l"(src));
}
__device__ __forceinline__ void cpa_commit() {
    asm volatile("cp.async.commit_group;\n" ::: "memory");
}
template <int N>
__device__ __forceinline__ void cpa_wait() {
    asm volatile("cp.async.wait_group %0;\n" :: "n"(N) : "memory");
}
__device__ __forceinline__ void ldsm4(uint32_t* r, uint32_t addr) {
    asm volatile("ldmatrix.sync.aligned.m8n8.x4.shared.b16 {%0,%1,%2,%3}, [%4];"
                 : "=r"(r[0]), "=r"(r[1]), "=r"(r[2]), "=r"(r[3]) : "r"(addr));
}
__device__ __forceinline__ void ldsm4t(uint32_t* r, uint32_t addr) {
    asm volatile("ldmatrix.sync.aligned.m8n8.x4.trans.shared.b16 {%0,%1,%2,%3}, [%4];"
                 : "=r"(r[0]), "=r"(r[1]), "=r"(r[2]), "=r"(r[3]) : "r"(addr));
}
__device__ __forceinline__ void ldsm2(uint32_t* r, uint32_t addr) {
    asm volatile("ldmatrix.sync.aligned.m8n8.x2.shared.b16 {%0,%1}, [%2];"
                 : "=r"(r[0]), "=r"(r[1]) : "r"(addr));
}
__device__ __forceinline__ void mma_bf16(float* c, const uint32_t* a, const uint32_t* b) {
    asm volatile("mma.sync.aligned.m16n8k16.row.col.f32.bf16.bf16.f32 "
                 "{%0,%1,%2,%3},{%4,%5,%6,%7},{%8,%9},{%0,%1,%2,%3};"
                 : "+f"(c[0]), "+f"(c[1]), "+f"(c[2]), "+f"(c[3])
                 : "r"(a[0]), "r"(a[1]), "r"(a[2]), "r"(a[3]), "r"(b[0]), "r"(b[1]));
}
__device__ __forceinline__ void split2x(float4 v, uint2& hv, uint2& lv) {
    __nv_bfloat16 h0 = __float2bfloat16(v.x), h1 = __float2bfloat16(v.y);
    __nv_bfloat16 h2 = __float2bfloat16(v.z), h3 = __float2bfloat16(v.w);
    __nv_bfloat16 l0 = __float2bfloat16(v.x - __bfloat162float(h0));
    __nv_bfloat16 l1 = __float2bfloat16(v.y - __bfloat162float(h1));
    __nv_bfloat16 l2 = __float2bfloat16(v.z - __bfloat162float(h2));
    __nv_bfloat16 l3 = __float2bfloat16(v.w - __bfloat162float(h3));
    hv = make_uint2((uint32_t)__bfloat16_as_ushort(h0) | ((uint32_t)__bfloat16_as_ushort(h1) << 16),
                    (uint32_t)__bfloat16_as_ushort(h2) | ((uint32_t)__bfloat16_as_ushort(h3) << 16));
    lv = make_uint2((uint32_t)__bfloat16_as_ushort(l0) | ((uint32_t)__bfloat16_as_ushort(l1) << 16),
                    (uint32_t)__bfloat16_as_ushort(l2) | ((uint32_t)__bfloat16_as_ushort(l3) << 16));
}
__device__ __forceinline__ void split4(__nv_bfloat16* hi, __nv_bfloat16* lo,
                                       int off, float4 v) {
    uint2 hv, lv;
    split2x(v, hv, lv);
    *(uint2*)(hi + off) = hv;
    *(uint2*)(lo + off) = lv;
}
__device__ __forceinline__ uint32_t pk2(float a, float b) {
    __nv_bfloat162 h = __floats2bfloat162_rn(a, b);
    return *(uint32_t*)&h;
}

__device__ __forceinline__ void stage_q(const float* Qh, int q0, int t,
                                        __nv_bfloat16* Qhi, __nv_bfloat16* Qlo) {
    for (int e = t; e < 128 * 16; e += 256) {
        int r = e >> 4, c4 = e & 15;
        float4 q4 = *(const float4*)(Qh + (size_t)(q0 + r) * D + (c4 << 2));
        q4.x *= SCALE; q4.y *= SCALE; q4.z *= SCALE; q4.w *= SCALE;
        split4(Qhi, Qlo, r * STR + (c4 << 2), q4);
    }
}
__device__ __forceinline__ void stage_k(const float* Kh, int k0, int t,
                                        __nv_bfloat16* Khi, __nv_bfloat16* Klo) {
    for (int e = t; e < 128 * 16; e += 256) {
        int r = e >> 4, c4 = e & 15;
        float4 k4 = *(const float4*)(Kh + (size_t)(k0 + r) * D + (c4 << 2));
        split4(Khi, Klo, r * STR + (c4 << 2), k4);
    }
}

// ---------------------------------------------------------------------------
// K1: stats — full-precision QK per 256-wide k-pair, rowsums -> g_stats.
// Masked-band CTAs zero-fill W and convert K/V tiles to bf16 scratch.
// ---------------------------------------------------------------------------
__global__ __launch_bounds__(256, 3)
void stats_mma(const float* __restrict__ Q, const float* __restrict__ Km,
               const float* __restrict__ Vm, float* __restrict__ W) {
    int p = blockIdx.x, qt = 15 - blockIdx.y, h = blockIdx.z;
    int kt0 = p << 1;
    int q0 = qt << 7;
    int t = threadIdx.x;
    float* Wh = W + (size_t)h * S * S;

    if (p == 0 && t == 0) g_cnt[(h << 4) + qt] = 0;   // reset emit counter

    if (kt0 > qt) {                      // masked band: final W is 0
        float4 z = make_float4(0.f, 0.f, 0.f, 0.f);
        int c0 = kt0 << 7;
        for (int e = t; e < 128 * 64; e += 256) {
            int r = e >> 6, c4 = e & 63;
            __stcs((float4*)(Wh + (size_t)(q0 + r) * S + c0 + (c4 << 2)), z);
        }
        // K/V bf16 conversion — exactly once per (h, tile-pair)
        int ct = -1;
        if (qt == kt0 - 1) ct = kt0;                 // tiles 2..15
        else if (kt0 == 14 && qt == 0) ct = 0;       // tiles 0, 1
        if (ct >= 0) {
            for (int tile = ct; tile < ct + 2; tile++) {
                const float* Ks = Km + (size_t)h * S * D + (size_t)tile * 128 * D;
                const float* Vs = Vm + (size_t)h * S * D + (size_t)tile * 128 * D;
                __nv_bfloat16* kb = g_kbf + ((size_t)(h * 16 + tile) * 2) * 8192;
                __nv_bfloat16* vb = g_vbf + ((size_t)(h * 16 + tile) * 2) * 8192;
                for (int e = t; e < 128 * 16; e += 256) {
                    int r = e >> 4, c4 = e & 15;
                    uint2 hv, lv;
                    split2x(*(const float4*)(Ks + r * D + (c4 << 2)), hv, lv);
                    *(uint2*)(kb + r * 64 + (c4 << 2)) = hv;
                    *(uint2*)(kb + 8192 + r * 64 + (c4 << 2)) = lv;
                    split2x(*(const float4*)(Vs + r * D + (c4 << 2)), hv, lv);
                    *(uint2*)(vb + r * 64 + (c4 << 2)) = hv;
                    *(uint2*)(vb + 8192 + r * 64 + (c4 << 2)) = lv;
                }
            }
        }
        return;
    }

    extern __shared__ char smraw[];
    __nv_bfloat16* Qhi = (__nv_bfloat16*)smraw;
    __nv_bfloat16* Qlo = Qhi + 128 * STR;
    __nv_bfloat16* Khi = Qlo + 128 * STR;
    __nv_bfloat16* Klo = Khi + 128 * STR;

    stage_q(Q + (size_t)h * S * D, q0, t, Qhi, Qlo);

    const float* Kh = Km + (size_t)h * S * D;
    int w = t >> 5, L = t & 31;
    int wr = w << 4;
    int g = L >> 2, q = L & 3;
    int gi0 = q0 + wr + g, gi1 = gi0 + 8;
    uint32_t qhiB = smem_u32(Qhi), qloB = smem_u32(Qlo);
    uint32_t khiB = smem_u32(Khi), kloB = smem_u32(Klo);

#pragma unroll 1
    for (int sub = 0; sub < 2; sub++) {
        int kt = kt0 + sub;
        if (kt > qt) break;
        int k0 = kt << 7;
        __syncthreads();
        stage_k(Kh, k0, t, Khi, Klo);
        __syncthreads();

        uint32_t ah[4][4], al[4][4];
#pragma unroll
        for (int kk = 0; kk < 4; kk++) {
            uint32_t aoff = (uint32_t)(((wr + (L & 15)) * STR + (kk << 4) + ((L >> 4) << 3)) << 1);
            ldsm4(ah[kk], qhiB + aoff);
            ldsm4(al[kk], qloB + aoff);
        }

        float s0 = 0.f, s1 = 0.f;
        bool diag = (kt == qt);
#pragma unroll
        for (int n = 0; n < 16; n++) {
            float acc[4] = {0.f, 0.f, 0.f, 0.f};
#pragma unroll
            for (int kk = 0; kk < 4; kk++) {
                uint32_t boff = (uint32_t)((((n << 3) + (L & 7)) * STR +
                                            (kk << 4) + (((L >> 3) & 1) << 3)) << 1);
                uint32_t bh[2], bl[2];
                ldsm2(bh, khiB + boff);
                ldsm2(bl, kloB + boff);
                mma_bf16(acc, ah[kk], bh);
                mma_bf16(acc, ah[kk], bl);
                mma_bf16(acc, al[kk], bh);
            }
            if (diag) {
                int cg = k0 + (n << 3) + (q << 1);
                s0 += ((cg > gi0) ? 0.f : __expf(acc[0])) +
                      ((cg + 1 > gi0) ? 0.f : __expf(acc[1]));
                s1 += ((cg > gi1) ? 0.f : __expf(acc[2])) +
                      ((cg + 1 > gi1) ? 0.f : __expf(acc[3]));
            } else {
                s0 += __expf(acc[0]) + __expf(acc[1]);
                s1 += __expf(acc[2]) + __expf(acc[3]);
            }
        }
        s0 += __shfl_xor_sync(0xffffffffu, s0, 1);
        s0 += __shfl_xor_sync(0xffffffffu, s0, 2);
        s1 += __shfl_xor_sync(0xffffffffu, s1, 1);
        s1 += __shfl_xor_sync(0xffffffffu, s1, 2);
        if (q == 0) {
            size_t sb = (size_t)(h * 16 + kt) * S;
            g_stats[sb + gi0] = s0;
            g_stats[sb + gi1] = s1;
        }
    }

    // odd-straddle: qt even & kt0 == qt -> tile kt0+1 is fully masked
    if (kt0 == qt && kt0 + 1 <= 15) {
        float4 z = make_float4(0.f, 0.f, 0.f, 0.f);
        int c0 = (kt0 + 1) << 7;
        for (int e = t; e < 128 * 32; e += 256) {
            int r = e >> 5, c4 = e & 31;
            __stcs((float4*)(Wh + (size_t)(q0 + r) * S + c0 + (c4 << 2)), z);
        }
    }
}

// ---------------------------------------------------------------------------
// K2: emit — cp.async double-buffered pipeline over 64-row half-tiles.
// acc_o lives in REGISTERS across all chunks (no smem accumulator).
// ---------------------------------------------------------------------------
__global__ __launch_bounds__(256, 2)
void emit_mma(const float* __restrict__ Q, float* __restrict__ W,
              float* __restrict__ O) {
    int p = blockIdx.x, qt = 15 - blockIdx.y, h = blockIdx.z;
    int kt0 = p << 2;
    if (kt0 > qt) return;
    float* Wh = W + (size_t)h * S * S;
    int q0 = qt << 7;
    int t = threadIdx.x;

    extern __shared__ char smraw[];
    __shared__ float Ls[128];
    __shared__ int isLast;

    if (t < 128) {
        float Lsum = 0.f;
        for (int k2 = 0; k2 <= qt; k2++)
            Lsum += g_stats[(size_t)(h * 16 + k2) * S + q0 + t];
        Ls[t] = 1.f / Lsum;
    }

    // stage Q temporarily, preload A fragments, then free the smem for buffers
    __nv_bfloat16* Qhi = (__nv_bfloat16*)smraw;
    __nv_bfloat16* Qlo = Qhi + 128 * STR;
    stage_q(Q + (size_t)h * S * D, q0, t, Qhi, Qlo);
    __syncthreads();

    int w = t >> 5, L = t & 31;
    int wr = w << 4;
    int g = L >> 2, q = L & 3;
    int gi0 = q0 + wr + g, gi1 = gi0 + 8;
    float li0 = Ls[wr + g], li1 = Ls[wr + 8 + g];

    uint32_t qhiB = smem_u32(Qhi), qloB = smem_u32(Qlo);
    uint32_t ahq[4][4], alq[4][4];
#pragma unroll
    for (int kk = 0; kk < 4; kk++) {
        uint32_t aoff = (uint32_t)(((wr + (L & 15)) * STR + (kk << 4) + ((L >> 4) << 3)) << 1);
        ldsm4(ahq[kk], qhiB + aoff);
        ldsm4(alq[kk], qloB + aoff);
    }
    __syncthreads();    // Q smem now reusable as pipeline buffers

    uint32_t sbase = smem_u32(smraw);
    int nsub = qt - kt0 + 1; if (nsub > 4) nsub = 4;
    int nch = nsub << 1;

    // issue cp.async loads for chunk c into buffer c&1
    auto issue = [&](int c) {
        int sub = c >> 1, half = c & 1, kt = kt0 + sub;
        uint32_t dst = sbase + (uint32_t)(c & 1) * 36864u;
        size_t kb = ((size_t)(h * 16 + kt) * 2) * 8192 + (size_t)half * 64 * 64;
#pragma unroll
        for (int i = 0; i < 8; i++) {
            int idx = t + (i << 8);
            int plane = idx >> 9;          // 0 Khi, 1 Klo, 2 Vhi, 3 Vlo
            int rem = idx & 511;
            int r = rem >> 3, c16 = rem & 7;
            const __nv_bfloat16* src = (plane < 2 ? g_kbf : g_vbf)
                + kb + (size_t)(plane & 1) * 8192 + r * 64 + (c16 << 3);
            cpa16(dst + (uint32_t)plane * 9216u + (uint32_t)(r * 144) + (uint32_t)(c16 << 4), src);
        }
    };

    issue(0); cpa_commit();

    // persistent PV accumulators (registers, across all chunks)
    float acc_o[8][4];
#pragma unroll
    for (int n = 0; n < 8; n++)
#pragma unroll
        for (int i = 0; i < 4; i++) acc_o[n][i] = 0.f;

#pragma unroll 1
    for (int c = 0; c < nch; c++) {
        if (c + 1 < nch) { issue(c + 1); cpa_commit(); cpa_wait<1>(); }
        else cpa_wait<0>();
        __syncthreads();

        uint32_t b = sbase + (uint32_t)(c & 1) * 36864u;
        uint32_t khiB = b, kloB = b + 9216u, vhiB = b + 18432u, vloB = b + 27648u;
        int sub = c >> 1, half = c & 1, kt = kt0 + sub;
        int k0c = (kt << 7) + (half << 6);
        bool diag = (kt == qt);

        // QK over this 64-col half: acc[8][4]
        float acc[8][4];
#pragma unroll
        for (int n = 0; n < 8; n++)
#pragma unroll
            for (int i = 0; i < 4; i++) acc[n][i] = 0.f;
#pragma unroll
        for (int kk = 0; kk < 4; kk++) {
#pragma unroll
            for (int n2 = 0; n2 < 4; n2++) {
                uint32_t boff = (uint32_t)((((n2 << 4) + ((L >> 4) << 3) + (L & 7)) * STR +
                                            (kk << 4) + (((L >> 3) & 1) << 3)) << 1);
                uint32_t bh[4], bl[4];
                ldsm4(bh, khiB + boff);
                ldsm4(bl, kloB + boff);
                mma_bf16(acc[2 * n2],     ahq[kk], &bh[0]);
                mma_bf16(acc[2 * n2],     ahq[kk], &bl[0]);
                mma_bf16(acc[2 * n2],     alq[kk], &bh[0]);
                mma_bf16(acc[2 * n2 + 1], ahq[kk], &bh[2]);
                mma_bf16(acc[2 * n2 + 1], ahq[kk], &bl[2]);
                mma_bf16(acc[2 * n2 + 1], alq[kk], &bh[2]);
            }
        }

        // epilogue: exp + W store + fused PV over this half's 64 j values
#pragma unroll
        for (int kk = 0; kk < 4; kk++) {
            float uE[4], uO[4];
#pragma unroll
            for (int h2 = 0; h2 < 2; h2++) {
                float* u = h2 ? uO : uE;
                int n = (kk << 1) + h2;
                int cg = k0c + (n << 3) + (q << 1);
                u[0] = (diag && cg > gi0) ? 0.f : __expf(acc[n][0]);
                u[1] = (diag && cg + 1 > gi0) ? 0.f : __expf(acc[n][1]);
                u[2] = (diag && cg > gi1) ? 0.f : __expf(acc[n][2]);
                u[3] = (diag && cg + 1 > gi1) ? 0.f : __expf(acc[n][3]);
                __stcs((float2*)(Wh + (size_t)gi0 * S + cg),
                       make_float2(u[0] * li0, u[1] * li0));
                __stcs((float2*)(Wh + (size_t)gi1 * S + cg),
                       make_float2(u[2] * li1, u[3] * li1));
            }
            uint32_t ah[4], al[4];
            ah[0] = pk2(uE[0], uE[1]); ah[1] = pk2(uE[2], uE[3]);
            ah[2] = pk2(uO[0], uO[1]); ah[3] = pk2(uO[2], uO[3]);
            al[0] = pk2(uE[0] - __bfloat162float(__float2bfloat16(uE[0])),
                        uE[1] - __bfloat162float(__float2bfloat16(uE[1])));
            al[1] = pk2(uE[2] - __bfloat162float(__float2bfloat16(uE[2])),
                        uE[3] - __bfloat162float(__float2bfloat16(uE[3])));
            al[2] = pk2(uO[0] - __bfloat162float(__float2bfloat16(uO[0])),
                        uO[1] - __bfloat162float(__float2bfloat16(uO[1])));
            al[3] = pk2(uO[2] - __bfloat162float(__float2bfloat16(uO[2])),
                        uO[3] - __bfloat162float(__float2bfloat16(uO[3])));

#pragma unroll
            for (int dn2 = 0; dn2 < 4; dn2++) {
                uint32_t boff = (uint32_t)((((kk << 4) + (L & 15)) * STR +
                                            (dn2 << 4) + (((L >> 4) & 1) << 3)) << 1);
                uint32_t bh[4], bl[4];
                ldsm4t(bh, vhiB + boff);
                ldsm4t(bl, vloB + boff);
                mma_bf16(acc_o[2 * dn2],     ah, &bh[0]);
                mma_bf16(acc_o[2 * dn2],     ah, &bl[0]);
                mma_bf16(acc_o[2 * dn2],     al, &bh[0]);
                mma_bf16(acc_o[2 * dn2 + 1], ah, &bh[2]);
                mma_bf16(acc_o[2 * dn2 + 1], ah, &bl[2]);
                mma_bf16(acc_o[2 * dn2 + 1], al, &bh[2]);
            }
        }
        __syncthreads();   // buffer c&1 free before issue(c+2) overwrites it
    }

    // raw quad-partial O directly from registers
    float* P = g_part + (((size_t)(h * 16 + qt) << 2) + p) * (128 * 64);
#pragma unroll
    for (int dn = 0; dn < 8; dn++) {
        int cc = (dn << 3) + (q << 1);
        *(float2*)(P + (wr + g) * 64 + cc) =
            make_float2(acc_o[dn][0], acc_o[dn][1]);
        *(float2*)(P + (wr + 8 + g) * 64 + cc) =
            make_float2(acc_o[dn][2], acc_o[dn][3]);
    }

    // last CTA for this (h, qt) reduces partials and writes O
    __threadfence();
    __syncthreads();
    int np = (qt >> 2) + 1;
    if (t == 0) {
        int old = atomicAdd(&g_cnt[(h << 4) + qt], 1);
        isLast = (old == np - 1) ? 1 : 0;
    }
    __syncthreads();
    if (isLast) {
        __threadfence();
        const float* Pb = g_part + ((size_t)(h * 16 + qt) << 2) * (128 * 64);
        float* Oh = O + (size_t)h * S * D;
        for (int f = t; f < 2048; f += 256) {
            float4 s = make_float4(0.f, 0.f, 0.f, 0.f);
            for (int pp = 0; pp < np; pp++) {
                float4 v = __ldcg((const float4*)(Pb + (size_t)pp * (128 * 64) + (f << 2)));
                s.x += v.x; s.y += v.y; s.z += v.z; s.w += v.w;
            }
            float li = Ls[f >> 4];
            *(float4*)(Oh + (size_t)q0 * D + (f << 2)) =
                make_float4(s.x * li, s.y * li, s.z * li, s.w * li);
        }
    }
}

// ---------------------------------------------------------------------------
// fallback (output-only branch)
// ---------------------------------------------------------------------------
__global__ void fallback_kernel(const float* __restrict__ Q,
                                const float* __restrict__ K,
                                const float* __restrict__ V,
                                float* __restrict__ O) {
    int i = blockIdx.x, h = blockIdx.y;
    const float* Qh = Q + (size_t)h * S * D;
    const float* Kh = K + (size_t)h * S * D;
    const float* Vh = V + (size_t)h * S * D;
    float* Oh = O + (size_t)h * S * D;
    __shared__ float p[S];
    __shared__ float qsh[D];
    __shared__ float red[64];
    int t = threadIdx.x;
    qsh[t] = Qh[(size_t)i * D + t];
    __syncthreads();
    float lsum = 0.f;
    for (int j = t; j <= i; j += 64) {
        const float* kr = Kh + (size_t)j * D;
        float s = 0.f;
#pragma unroll 16
        for (int d = 0; d < D; d++) s = fmaf(qsh[d], kr[d], s);
        float e = __expf(s * SCALE);
        p[j] = e; lsum += e;
    }
    red[t] = lsum; __syncthreads();
    for (int s2 = 32; s2 > 0; s2 >>= 1) { if (t < s2) red[t] += red[t + s2]; __syncthreads(); }
    float inv = 1.0f / red[0];
    __syncthreads();
    float o = 0.f;
    for (int j = 0; j <= i; j++) o = fmaf(p[j], Vh[(size_t)j * D + t], o);
    Oh[(size_t)i * D + t] = o * inv;
}

// ---------------------------------------------------------------------------
extern "C" void kernel_launch(void* const* d_in, const int* in_sizes, int n_in,
                              void* d_out, int out_size) {
    const float* Q = (const float*)d_in[0];
    const float* K = (const float*)d_in[1];
    const float* V = (const float*)d_in[2];
    float* out = (float*)d_out;

    const long long O_ELEMS = (long long)NH * S * D;
    const long long W_ELEMS = (long long)NH * S * S;

    const int SMEM_TILES = 4 * 128 * STR * 2;   // 73728 B
    cudaFuncSetAttribute(stats_mma, cudaFuncAttributeMaxDynamicSharedMemorySize, SMEM_TILES);
    cudaFuncSetAttribute(emit_mma,  cudaFuncAttributeMaxDynamicSharedMemorySize, SMEM_TILES);

    if ((long long)out_size >= O_ELEMS + W_ELEMS) {
        float* W = out + O_ELEMS;
        stats_mma<<<dim3(8, 16, 32), 256, SMEM_TILES>>>(Q, K, V, W);
        emit_mma<<<dim3(4, 16, 32), 256, SMEM_TILES>>>(Q, W, out);
    } else if ((long long)out_size == W_ELEMS) {
        float* W = out;
        float* Oscratch;
        cudaGetSymbolAddress((void**)&Oscratch, g_Oscratch);
        stats_mma<<<dim3(8, 16, 32), 256, SMEM_TILES>>>(Q, K, V, W);
        emit_mma<<<dim3(4, 16, 32), 256, SMEM_TILES>>>(Q, W, Oscratch);
    } else {
        fallback_kernel<<<dim3(S, NH), 64>>>(Q, K, V, out);
    }
}

// round 16
// speedup vs baseline: 1.0911x; 1.0002x over previous
#include <cuda_runtime.h>
#include <cuda_bf16.h>
#include <math.h>
#include <stdint.h>

#define S 2048
#define D 64
#define NH 32
#define SCALE 0.125f
#define STR 72            // smem row stride in bf16 (64 data + 8 pad)

// per-(head, 128-wide k-tile, row) partial sums of exp(s)
__device__ float g_stats[(size_t)NH * 16 * S];
// split-K partial O over 512-wide k-quads: [h][qt][p<4][128*64]
__device__ float g_part[(size_t)NH * 16 * 4 * 128 * 64];
// completion counters per (h, qt)
__device__ int g_cnt[NH * 16];
// scratch O for the weights-only branch
__device__ float g_Oscratch[(size_t)NH * S * D];
// pre-split bf16 K/V: [h][tile][plane hi/lo][128][64]
__device__ __align__(16) __nv_bfloat16 g_kbf[(size_t)NH * 16 * 2 * 128 * 64];
__device__ __align__(16) __nv_bfloat16 g_vbf[(size_t)NH * 16 * 2 * 128 * 64];

// ------------------------------ helpers -----------------------------------
__device__ __forceinline__ uint32_t smem_u32(const void* p) {
    return (uint32_t)__cvta_generic_to_shared(p);
}
__device__ __forceinline__ void cpa16(uint32_t dst, const void* src) {
    asm volatile("cp.async.ca.shared.global [%0], [%1], 16;\n" :: "r"(dst), "l"(src));
}
__device__ __forceinline__ void cpa_commit() {
    asm volatile("cp.async.commit_group;\n" ::: "memory");
}
template <int N>
__device__ __forceinline__ void cpa_wait() {
    asm volatile("cp.async.wait_group %0;\n" :: "n"(N) : "memory");
}
__device__ __forceinline__ void ldsm4(uint32_t* r, uint32_t addr) {
    asm volatile("ldmatrix.sync.aligned.m8n8.x4.shared.b16 {%0,%1,%2,%3}, [%4];"
                 : "=r"(r[0]), "=r"(r[1]), "=r"(r[2]), "=r"(r[3]) : "r"(addr));
}
__device__ __forceinline__ void ldsm4t(uint32_t* r, uint32_t addr) {
    asm volatile("ldmatrix.sync.aligned.m8n8.x4.trans.shared.b16 {%0,%1,%2,%3}, [%4];"
                 : "=r"(r[0]), "=r"(r[1]), "=r"(r[2]), "=r"(r[3]) : "r"(addr));
}
__device__ __forceinline__ void ldsm2(uint32_t* r, uint32_t addr) {
    asm volatile("ldmatrix.sync.aligned.m8n8.x2.shared.b16 {%0,%1}, [%2];"
                 : "=r"(r[0]), "=r"(r[1]) : "r"(addr));
}
__device__ __forceinline__ void mma_bf16(float* c, const uint32_t* a, const uint32_t* b) {
    asm volatile("mma.sync.aligned.m16n8k16.row.col.f32.bf16.bf16.f32 "
                 "{%0,%1,%2,%3},{%4,%5,%6,%7},{%8,%9},{%0,%1,%2,%3};"
                 : "+f"(c[0]), "+f"(c[1]), "+f"(c[2]), "+f"(c[3])
                 : "r"(a[0]), "r"(a[1]), "r"(a[2]), "r"(a[3]), "r"(b[0]), "r"(b[1]));
}
__device__ __forceinline__ void split2x(float4 v, uint2& hv, uint2& lv) {
    __nv_bfloat16 h0 = __float2bfloat16(v.x), h1 = __float2bfloat16(v.y);
    __nv_bfloat16 h2 = __float2bfloat16(v.z), h3 = __float2bfloat16(v.w);
    __nv_bfloat16 l0 = __float2bfloat16(v.x - __bfloat162float(h0));
    __nv_bfloat16 l1 = __float2bfloat16(v.y - __bfloat162float(h1));
    __nv_bfloat16 l2 = __float2bfloat16(v.z - __bfloat162float(h2));
    __nv_bfloat16 l3 = __float2bfloat16(v.w - __bfloat162float(h3));
    hv = make_uint2((uint32_t)__bfloat16_as_ushort(h0) | ((uint32_t)__bfloat16_as_ushort(h1) << 16),
                    (uint32_t)__bfloat16_as_ushort(h2) | ((uint32_t)__bfloat16_as_ushort(h3) << 16));
    lv = make_uint2((uint32_t)__bfloat16_as_ushort(l0) | ((uint32_t)__bfloat16_as_ushort(l1) << 16),
                    (uint32_t)__bfloat16_as_ushort(l2) | ((uint32_t)__bfloat16_as_ushort(l3) << 16));
}
__device__ __forceinline__ void split4(__nv_bfloat16* hi, __nv_bfloat16* lo,
                                       int off, float4 v) {
    uint2 hv, lv;
    split2x(v, hv, lv);
    *(uint2*)(hi + off) = hv;
    *(uint2*)(lo + off) = lv;
}
__device__ __forceinline__ uint32_t pk2(float a, float b) {
    __nv_bfloat162 h = __floats2bfloat162_rn(a, b);
    return *(uint32_t*)&h;
}

__device__ __forceinline__ void stage_q(const float* Qh, int q0, int t,
                                        __nv_bfloat16* Qhi, __nv_bfloat16* Qlo) {
    for (int e = t; e < 128 * 16; e += 256) {
        int r = e >> 4, c4 = e & 15;
        float4 q4 = *(const float4*)(Qh + (size_t)(q0 + r) * D + (c4 << 2));
        q4.x *= SCALE; q4.y *= SCALE; q4.z *= SCALE; q4.w *= SCALE;
        split4(Qhi, Qlo, r * STR + (c4 << 2), q4);
    }
}
__device__ __forceinline__ void stage_k(const float* Kh, int k0, int t,
                                        __nv_bfloat16* Khi, __nv_bfloat16* Klo) {
    for (int e = t; e < 128 * 16; e += 256) {
        int r = e >> 4, c4 = e & 15;
        float4 k4 = *(const float4*)(Kh + (size_t)(k0 + r) * D + (c4 << 2));
        split4(Khi, Klo, r * STR + (c4 << 2), k4);
    }
}

// ---------------------------------------------------------------------------
// K1: stats — full-precision QK per 256-wide k-pair, rowsums -> g_stats.
// Masked-band CTAs zero-fill W and convert K/V tiles to bf16 scratch.
// ---------------------------------------------------------------------------
__global__ __launch_bounds__(256, 3)
void stats_mma(const float* __restrict__ Q, const float* __restrict__ Km,
               const float* __restrict__ Vm, float* __restrict__ W) {
    int p = blockIdx.x, qt = 15 - blockIdx.y, h = blockIdx.z;
    int kt0 = p << 1;
    int q0 = qt << 7;
    int t = threadIdx.x;
    float* Wh = W + (size_t)h * S * S;

    if (p == 0 && t == 0) g_cnt[(h << 4) + qt] = 0;   // reset emit counter

    if (kt0 > qt) {                      // masked band: final W is 0
        float4 z = make_float4(0.f, 0.f, 0.f, 0.f);
        int c0 = kt0 << 7;
        for (int e = t; e < 128 * 64; e += 256) {
            int r = e >> 6, c4 = e & 63;
            __stcs((float4*)(Wh + (size_t)(q0 + r) * S + c0 + (c4 << 2)), z);
        }
        // K/V bf16 conversion — exactly once per (h, tile-pair)
        int ct = -1;
        if (qt == kt0 - 1) ct = kt0;                 // tiles 2..15
        else if (kt0 == 14 && qt == 0) ct = 0;       // tiles 0, 1
        if (ct >= 0) {
            for (int tile = ct; tile < ct + 2; tile++) {
                const float* Ks = Km + (size_t)h * S * D + (size_t)tile * 128 * D;
                const float* Vs = Vm + (size_t)h * S * D + (size_t)tile * 128 * D;
                __nv_bfloat16* kb = g_kbf + ((size_t)(h * 16 + tile) * 2) * 8192;
                __nv_bfloat16* vb = g_vbf + ((size_t)(h * 16 + tile) * 2) * 8192;
                for (int e = t; e < 128 * 16; e += 256) {
                    int r = e >> 4, c4 = e & 15;
                    uint2 hv, lv;
                    split2x(*(const float4*)(Ks + r * D + (c4 << 2)), hv, lv);
                    *(uint2*)(kb + r * 64 + (c4 << 2)) = hv;
                    *(uint2*)(kb + 8192 + r * 64 + (c4 << 2)) = lv;
                    split2x(*(const float4*)(Vs + r * D + (c4 << 2)), hv, lv);
                    *(uint2*)(vb + r * 64 + (c4 << 2)) = hv;
                    *(uint2*)(vb + 8192 + r * 64 + (c4 << 2)) = lv;
                }
            }
        }
        return;
    }

    extern __shared__ char smraw[];
    __nv_bfloat16* Qhi = (__nv_bfloat16*)smraw;
    __nv_bfloat16* Qlo = Qhi + 128 * STR;
    __nv_bfloat16* Khi = Qlo + 128 * STR;
    __nv_bfloat16* Klo = Khi + 128 * STR;

    stage_q(Q + (size_t)h * S * D, q0, t, Qhi, Qlo);

    const float* Kh = Km + (size_t)h * S * D;
    int w = t >> 5, L = t & 31;
    int wr = w << 4;
    int g = L >> 2, q = L & 3;
    int gi0 = q0 + wr + g, gi1 = gi0 + 8;
    uint32_t qhiB = smem_u32(Qhi), qloB = smem_u32(Qlo);
    uint32_t khiB = smem_u32(Khi), kloB = smem_u32(Klo);

#pragma unroll 1
    for (int sub = 0; sub < 2; sub++) {
        int kt = kt0 + sub;
        if (kt > qt) break;
        int k0 = kt << 7;
        __syncthreads();
        stage_k(Kh, k0, t, Khi, Klo);
        __syncthreads();

        uint32_t ah[4][4], al[4][4];
#pragma unroll
        for (int kk = 0; kk < 4; kk++) {
            uint32_t aoff = (uint32_t)(((wr + (L & 15)) * STR + (kk << 4) + ((L >> 4) << 3)) << 1);
            ldsm4(ah[kk], qhiB + aoff);
            ldsm4(al[kk], qloB + aoff);
        }

        float s0 = 0.f, s1 = 0.f;
        bool diag = (kt == qt);
#pragma unroll
        for (int n = 0; n < 16; n++) {
            float acc[4] = {0.f, 0.f, 0.f, 0.f};
#pragma unroll
            for (int kk = 0; kk < 4; kk++) {
                uint32_t boff = (uint32_t)((((n << 3) + (L & 7)) * STR +
                                            (kk << 4) + (((L >> 3) & 1) << 3)) << 1);
                uint32_t bh[2], bl[2];
                ldsm2(bh, khiB + boff);
                ldsm2(bl, kloB + boff);
                mma_bf16(acc, ah[kk], bh);
                mma_bf16(acc, ah[kk], bl);
                mma_bf16(acc, al[kk], bh);
            }
            if (diag) {
                int cg = k0 + (n << 3) + (q << 1);
                s0 += ((cg > gi0) ? 0.f : __expf(acc[0])) +
                      ((cg + 1 > gi0) ? 0.f : __expf(acc[1]));
                s1 += ((cg > gi1) ? 0.f : __expf(acc[2])) +
                      ((cg + 1 > gi1) ? 0.f : __expf(acc[3]));
            } else {
                s0 += __expf(acc[0]) + __expf(acc[1]);
                s1 += __expf(acc[2]) + __expf(acc[3]);
            }
        }
        s0 += __shfl_xor_sync(0xffffffffu, s0, 1);
        s0 += __shfl_xor_sync(0xffffffffu, s0, 2);
        s1 += __shfl_xor_sync(0xffffffffu, s1, 1);
        s1 += __shfl_xor_sync(0xffffffffu, s1, 2);
        if (q == 0) {
            size_t sb = (size_t)(h * 16 + kt) * S;
            g_stats[sb + gi0] = s0;
            g_stats[sb + gi1] = s1;
        }
    }

    // odd-straddle: qt even & kt0 == qt -> tile kt0+1 is fully masked
    if (kt0 == qt && kt0 + 1 <= 15) {
        float4 z = make_float4(0.f, 0.f, 0.f, 0.f);
        int c0 = (kt0 + 1) << 7;
        for (int e = t; e < 128 * 32; e += 256) {
            int r = e >> 5, c4 = e & 31;
            __stcs((float4*)(Wh + (size_t)(q0 + r) * S + c0 + (c4 << 2)), z);
        }
    }
}

// ---------------------------------------------------------------------------
// K2: emit — cp.async double-buffered pipeline over 64-row half-tiles.
// acc_o lives in REGISTERS across all chunks (no smem accumulator).
// ---------------------------------------------------------------------------
__global__ __launch_bounds__(256, 2)
void emit_mma(const float* __restrict__ Q, float* __restrict__ W,
              float* __restrict__ O) {
    int p = blockIdx.x, qt = 15 - blockIdx.y, h = blockIdx.z;
    int kt0 = p << 2;
    if (kt0 > qt) return;
    float* Wh = W + (size_t)h * S * S;
    int q0 = qt << 7;
    int t = threadIdx.x;

    extern __shared__ char smraw[];
    __shared__ float Ls[128];
    __shared__ int isLast;

    if (t < 128) {
        float Lsum = 0.f;
        for (int k2 = 0; k2 <= qt; k2++)
            Lsum += g_stats[(size_t)(h * 16 + k2) * S + q0 + t];
        Ls[t] = 1.f / Lsum;
    }

    // stage Q temporarily, preload A fragments, then free the smem for buffers
    __nv_bfloat16* Qhi = (__nv_bfloat16*)smraw;
    __nv_bfloat16* Qlo = Qhi + 128 * STR;
    stage_q(Q + (size_t)h * S * D, q0, t, Qhi, Qlo);
    __syncthreads();

    int w = t >> 5, L = t & 31;
    int wr = w << 4;
    int g = L >> 2, q = L & 3;
    int gi0 = q0 + wr + g, gi1 = gi0 + 8;
    float li0 = Ls[wr + g], li1 = Ls[wr + 8 + g];

    uint32_t qhiB = smem_u32(Qhi), qloB = smem_u32(Qlo);
    uint32_t ahq[4][4], alq[4][4];
#pragma unroll
    for (int kk = 0; kk < 4; kk++) {
        uint32_t aoff = (uint32_t)(((wr + (L & 15)) * STR + (kk << 4) + ((L >> 4) << 3)) << 1);
        ldsm4(ahq[kk], qhiB + aoff);
        ldsm4(alq[kk], qloB + aoff);
    }
    __syncthreads();    // Q smem now reusable as pipeline buffers

    uint32_t sbase = smem_u32(smraw);
    int nsub = qt - kt0 + 1; if (nsub > 4) nsub = 4;
    int nch = nsub << 1;

    // issue cp.async loads for chunk c into buffer c&1
    auto issue = [&](int c) {
        int sub = c >> 1, half = c & 1, kt = kt0 + sub;
        uint32_t dst = sbase + (uint32_t)(c & 1) * 36864u;
        size_t kb = ((size_t)(h * 16 + kt) * 2) * 8192 + (size_t)half * 64 * 64;
#pragma unroll
        for (int i = 0; i < 8; i++) {
            int idx = t + (i << 8);
            int plane = idx >> 9;          // 0 Khi, 1 Klo, 2 Vhi, 3 Vlo
            int rem = idx & 511;
            int r = rem >> 3, c16 = rem & 7;
            const __nv_bfloat16* src = (plane < 2 ? g_kbf : g_vbf)
                + kb + (size_t)(plane & 1) * 8192 + r * 64 + (c16 << 3);
            cpa16(dst + (uint32_t)plane * 9216u + (uint32_t)(r * 144) + (uint32_t)(c16 << 4), src);
        }
    };

    issue(0); cpa_commit();

    // persistent PV accumulators (registers, across all chunks)
    float acc_o[8][4];
#pragma unroll
    for (int n = 0; n < 8; n++)
#pragma unroll
        for (int i = 0; i < 4; i++) acc_o[n][i] = 0.f;

#pragma unroll 1
    for (int c = 0; c < nch; c++) {
        if (c + 1 < nch) { issue(c + 1); cpa_commit(); cpa_wait<1>(); }
        else cpa_wait<0>();
        __syncthreads();

        uint32_t b = sbase + (uint32_t)(c & 1) * 36864u;
        uint32_t khiB = b, kloB = b + 9216u, vhiB = b + 18432u, vloB = b + 27648u;
        int sub = c >> 1, half = c & 1, kt = kt0 + sub;
        int k0c = (kt << 7) + (half << 6);
        bool diag = (kt == qt);

        // QK over this 64-col half: acc[8][4]
        float acc[8][4];
#pragma unroll
        for (int n = 0; n < 8; n++)
#pragma unroll
            for (int i = 0; i < 4; i++) acc[n][i] = 0.f;
#pragma unroll
        for (int kk = 0; kk < 4; kk++) {
#pragma unroll
            for (int n2 = 0; n2 < 4; n2++) {
                uint32_t boff = (uint32_t)((((n2 << 4) + ((L >> 4) << 3) + (L & 7)) * STR +
                                            (kk << 4) + (((L >> 3) & 1) << 3)) << 1);
                uint32_t bh[4], bl[4];
                ldsm4(bh, khiB + boff);
                ldsm4(bl, kloB + boff);
                mma_bf16(acc[2 * n2],     ahq[kk], &bh[0]);
                mma_bf16(acc[2 * n2],     ahq[kk], &bl[0]);
                mma_bf16(acc[2 * n2],     alq[kk], &bh[0]);
                mma_bf16(acc[2 * n2 + 1], ahq[kk], &bh[2]);
                mma_bf16(acc[2 * n2 + 1], ahq[kk], &bl[2]);
                mma_bf16(acc[2 * n2 + 1], alq[kk], &bh[2]);
            }
        }

        // epilogue: exp + W store + fused PV over this half's 64 j values
#pragma unroll
        for (int kk = 0; kk < 4; kk++) {
            float uE[4], uO[4];
#pragma unroll
            for (int h2 = 0; h2 < 2; h2++) {
                float* u = h2 ? uO : uE;
                int n = (kk << 1) + h2;
                int cg = k0c + (n << 3) + (q << 1);
                u[0] = (diag && cg > gi0) ? 0.f : __expf(acc[n][0]);
                u[1] = (diag && cg + 1 > gi0) ? 0.f : __expf(acc[n][1]);
                u[2] = (diag && cg > gi1) ? 0.f : __expf(acc[n][2]);
                u[3] = (diag && cg + 1 > gi1) ? 0.f : __expf(acc[n][3]);
                __stcs((float2*)(Wh + (size_t)gi0 * S + cg),
                       make_float2(u[0] * li0, u[1] * li0));
                __stcs((float2*)(Wh + (size_t)gi1 * S + cg),
                       make_float2(u[2] * li1, u[3] * li1));
            }
            uint32_t ah[4], al[4];
            ah[0] = pk2(uE[0], uE[1]); ah[1] = pk2(uE[2], uE[3]);
            ah[2] = pk2(uO[0], uO[1]); ah[3] = pk2(uO[2], uO[3]);
            al[0] = pk2(uE[0] - __bfloat162float(__float2bfloat16(uE[0])),
                        uE[1] - __bfloat162float(__float2bfloat16(uE[1])));
            al[1] = pk2(uE[2] - __bfloat162float(__float2bfloat16(uE[2])),
                        uE[3] - __bfloat162float(__float2bfloat16(uE[3])));
            al[2] = pk2(uO[0] - __bfloat162float(__float2bfloat16(uO[0])),
                        uO[1] - __bfloat162float(__float2bfloat16(uO[1])));
            al[3] = pk2(uO[2] - __bfloat162float(__float2bfloat16(uO[2])),
                        uO[3] - __bfloat162float(__float2bfloat16(uO[3])));

#pragma unroll
            for (int dn2 = 0; dn2 < 4; dn2++) {
                uint32_t boff = (uint32_t)((((kk << 4) + (L & 15)) * STR +
                                            (dn2 << 4) + (((L >> 4) & 1) << 3)) << 1);
                uint32_t bh[4], bl[4];
                ldsm4t(bh, vhiB + boff);
                ldsm4t(bl, vloB + boff);
                mma_bf16(acc_o[2 * dn2],     ah, &bh[0]);
                mma_bf16(acc_o[2 * dn2],     ah, &bl[0]);
                mma_bf16(acc_o[2 * dn2],     al, &bh[0]);
                mma_bf16(acc_o[2 * dn2 + 1], ah, &bh[2]);
                mma_bf16(acc_o[2 * dn2 + 1], ah, &bl[2]);
                mma_bf16(acc_o[2 * dn2 + 1], al, &bh[2]);
            }
        }
        __syncthreads();   // buffer c&1 free before issue(c+2) overwrites it
    }

    // raw quad-partial O directly from registers
    float* P = g_part + (((size_t)(h * 16 + qt) << 2) + p) * (128 * 64);
#pragma unroll
    for (int dn = 0; dn < 8; dn++) {
        int cc = (dn << 3) + (q << 1);
        *(float2*)(P + (wr + g) * 64 + cc) =
            make_float2(acc_o[dn][0], acc_o[dn][1]);
        *(float2*)(P + (wr + 8 + g) * 64 + cc) =
            make_float2(acc_o[dn][2], acc_o[dn][3]);
    }

    // last CTA for this (h, qt) reduces partials and writes O
    __threadfence();
    __syncthreads();
    int np = (qt >> 2) + 1;
    if (t == 0) {
        int old = atomicAdd(&g_cnt[(h << 4) + qt], 1);
        isLast = (old == np - 1) ? 1 : 0;
    }
    __syncthreads();
    if (isLast) {
        __threadfence();
        const float* Pb = g_part + ((size_t)(h * 16 + qt) << 2) * (128 * 64);
        float* Oh = O + (size_t)h * S * D;
        for (int f = t; f < 2048; f += 256) {
            float4 s = make_float4(0.f, 0.f, 0.f, 0.f);
            for (int pp = 0; pp < np; pp++) {
                float4 v = __ldcg((const float4*)(Pb + (size_t)pp * (128 * 64) + (f << 2)));
                s.x += v.x; s.y += v.y; s.z += v.z; s.w += v.w;
            }
            float li = Ls[f >> 4];
            *(float4*)(Oh + (size_t)q0 * D + (f << 2)) =
                make_float4(s.x * li, s.y * li, s.z * li, s.w * li);
        }
    }
}

// ---------------------------------------------------------------------------
// fallback (output-only branch)
// ---------------------------------------------------------------------------
__global__ void fallback_kernel(const float* __restrict__ Q,
                                const float* __restrict__ K,
                                const float* __restrict__ V,
                                float* __restrict__ O) {
    int i = blockIdx.x, h = blockIdx.y;
    const float* Qh = Q + (size_t)h * S * D;
    const float* Kh = K + (size_t)h * S * D;
    const float* Vh = V + (size_t)h * S * D;
    float* Oh = O + (size_t)h * S * D;
    __shared__ float p[S];
    __shared__ float qsh[D];
    __shared__ float red[64];
    int t = threadIdx.x;
    qsh[t] = Qh[(size_t)i * D + t];
    __syncthreads();
    float lsum = 0.f;
    for (int j = t; j <= i; j += 64) {
        const float* kr = Kh + (size_t)j * D;
        float s = 0.f;
#pragma unroll 16
        for (int d = 0; d < D; d++) s = fmaf(qsh[d], kr[d], s);
        float e = __expf(s * SCALE);
        p[j] = e; lsum += e;
    }
    red[t] = lsum; __syncthreads();
    for (int s2 = 32; s2 > 0; s2 >>= 1) { if (t < s2) red[t] += red[t + s2]; __syncthreads(); }
    float inv = 1.0f / red[0];
    __syncthreads();
    float o = 0.f;
    for (int j = 0; j <= i; j++) o = fmaf(p[j], Vh[(size_t)j * D + t], o);
    Oh[(size_t)i * D + t] = o * inv;
}

// ---------------------------------------------------------------------------
extern "C" void kernel_launch(void* const* d_in, const int* in_sizes, int n_in,
                              void* d_out, int out_size) {
    const float* Q = (const float*)d_in[0];
    const float* K = (const float*)d_in[1];
    const float* V = (const float*)d_in[2];
    float* out = (float*)d_out;

    const long long O_ELEMS = (long long)NH * S * D;
    const long long W_ELEMS = (long long)NH * S * S;

    const int SMEM_TILES = 4 * 128 * STR * 2;   // 73728 B
    cudaFuncSetAttribute(stats_mma, cudaFuncAttributeMaxDynamicSharedMemorySize, SMEM_TILES);
    cudaFuncSetAttribute(emit_mma,  cudaFuncAttributeMaxDynamicSharedMemorySize, SMEM_TILES);

    if ((long long)out_size >= O_ELEMS + W_ELEMS) {
        float* W = out + O_ELEMS;
        stats_mma<<<dim3(8, 16, 32), 256, SMEM_TILES>>>(Q, K, V, W);
        emit_mma<<<dim3(4, 16, 32), 256, SMEM_TILES>>>(Q, W, out);
    } else if ((long long)out_size == W_ELEMS) {
        float* W = out;
        float* Oscratch;
        cudaGetSymbolAddress((void**)&Oscratch, g_Oscratch);
        stats_mma<<<dim3(8, 16, 32), 256, SMEM_TILES>>>(Q, K, V, W);
        emit_mma<<<dim3(4, 16, 32), 256, SMEM_TILES>>>(Q, W, Oscratch);
    } else {
        fallback_kernel<<<dim3(S, NH), 64>>>(Q, K, V, out);
    }
}